// round 5
// baseline (speedup 1.0000x reference)
#include <cuda_runtime.h>
#include <cuda_bf16.h>
#include <stdint.h>

// ---------------- problem constants ----------------
#define NB   64      // batch
#define CIN  128
#define HIN  56
#define WIN  56
#define CO   256
#define OHW  28
#define P    784     // 28*28
#define HW   3136    // 56*56
#define NPIX (NB*HW)         // 200704
#define NTOT (NB*P)          // 50176 output pixels
#define NOUT (NB*CO*P)       // 12845056
#define CNT_W1 294912.0f
#define CNT_W2 589824.0f
#define CNT_WS 32768.0f

// ---------------- scratch (device globals; no allocations allowed) ----------
__device__ uint4  g_xb [NB*HW];                 // packed sign bits of x (3.2MB)
__device__ uint4  g_wb1[CO*9];                  // packed w1 signs
__device__ uint4  g_wb2[CO*9*2];                // packed w2 signs (256b per co,tap)
__device__ uint4  g_wbs[CO];                    // packed ws signs
__device__ __align__(16) short g_c1[NOUT];      // conv1 integer result (25.7MB)
__device__ __align__(16) short g_sc[NOUT];      // shortcut integer result (25.7MB)
__device__ __align__(16) short g_c2[NOUT];      // conv2 integer result (25.7MB)
__device__ uint4  g_xb2[NTOT*2];                // packed BN1-output signs (1.6MB)
__device__ float  g_apart[112];                 // alpha block partials
__device__ float  g_alpha[3];                   // a1, a2, as
__device__ int       g_p1s[4*CO];               // BN1 stats partials
__device__ long long g_p1q[4*CO];
__device__ long long g_p2 [4*CO*5];             // BN2 stats partials (5 sums)
__device__ float  g_A1[CO], g_B1[CO];           // BN1 folded: v = A1*s + B1
__device__ float  g_cA[CO], g_cS[CO], g_cB[CO]; // out = cA*s2 + cS*sc + cB

__device__ __forceinline__ uint4 ldg4(const uint4* p) { return __ldg(p); }

// ---------------- kernels ----------------

// alpha partials: 8192-elem chunks, block reduce, deterministic partial store
__global__ void alpha_reduce_kernel(const float* __restrict__ w1,
                                    const float* __restrict__ w2,
                                    const float* __restrict__ ws) {
    int b = blockIdx.x;
    const float* src; int off;
    if (b < 36)       { src = w1; off = b * 8192; }
    else if (b < 108) { src = w2; off = (b - 36) * 8192; }
    else              { src = ws; off = (b - 108) * 8192; }
    float s = 0.0f;
    for (int i = threadIdx.x; i < 8192; i += 256) s += fabsf(src[off + i]);
    __shared__ float red[256];
    red[threadIdx.x] = s; __syncthreads();
    for (int st = 128; st > 0; st >>= 1) {
        if (threadIdx.x < st) red[threadIdx.x] += red[threadIdx.x + st];
        __syncthreads();
    }
    if (threadIdx.x == 0) g_apart[b] = red[0];
}

// pack sign(x): bit=1 means negative (sign(0)=+1 matches ref)
__global__ void pack_x_kernel(const float* __restrict__ x) {
    int idx = blockIdx.x * 256 + threadIdx.x;
    if (idx >= NPIX) return;
    int n = idx / HW, hw = idx % HW;
    unsigned wd[4] = {0u, 0u, 0u, 0u};
    const float* px = x + (size_t)n * CIN * HW + hw;
#pragma unroll 4
    for (int c = 0; c < CIN; c++) {
        unsigned neg = (px[(size_t)c * HW] < 0.0f) ? 1u : 0u;
        wd[c >> 5] |= neg << (c & 31);
    }
    g_xb[idx] = make_uint4(wd[0], wd[1], wd[2], wd[3]);
}

__global__ void pack_w_kernel(const float* __restrict__ w1,
                              const float* __restrict__ w2,
                              const float* __restrict__ ws) {
    int i = blockIdx.x * 256 + threadIdx.x;
    if (i < 2304) {                       // w1: i = co*9 + tap
        int co = i / 9, t = i % 9;
        unsigned wd[4] = {0u, 0u, 0u, 0u};
        for (int c = 0; c < CIN; c++) {
            unsigned neg = (w1[((size_t)co * CIN + c) * 9 + t] < 0.0f) ? 1u : 0u;
            wd[c >> 5] |= neg << (c & 31);
        }
        g_wb1[i] = make_uint4(wd[0], wd[1], wd[2], wd[3]);
    } else if (i < 4608) {                // w2
        int j = i - 2304; int co = j / 9, t = j % 9;
        unsigned wd[8] = {0u,0u,0u,0u,0u,0u,0u,0u};
        for (int c = 0; c < CO; c++) {
            unsigned neg = (w2[((size_t)co * CO + c) * 9 + t] < 0.0f) ? 1u : 0u;
            wd[c >> 5] |= neg << (c & 31);
        }
        g_wb2[(size_t)j * 2]     = make_uint4(wd[0], wd[1], wd[2], wd[3]);
        g_wb2[(size_t)j * 2 + 1] = make_uint4(wd[4], wd[5], wd[6], wd[7]);
    } else if (i < 4864) {                // ws
        int co = i - 4608;
        unsigned wd[4] = {0u, 0u, 0u, 0u};
        for (int c = 0; c < CIN; c++) {
            unsigned neg = (ws[(size_t)co * CIN + c] < 0.0f) ? 1u : 0u;
            wd[c >> 5] |= neg << (c & 31);
        }
        g_wbs[co] = make_uint4(wd[0], wd[1], wd[2], wd[3]);
    }
}

// conv1 (3x3 s2 p1, 128->256) + 1x1 s2 shortcut; 64 output channels per block
__global__ void __launch_bounds__(128) conv1_kernel() {
    __shared__ uint4 sw[64 * 9];
    __shared__ uint4 sws[64];
    int cb = blockIdx.y * 64;
    for (int i = threadIdx.x; i < 64 * 9; i += 128) sw[i] = ldg4(&g_wb1[cb * 9 + i]);
    if (threadIdx.x < 64) sws[threadIdx.x] = ldg4(&g_wbs[cb + threadIdx.x]);
    __syncthreads();
    int pg = blockIdx.x * 128 + threadIdx.x;
    if (pg >= NTOT) return;
    int n = pg / P, p = pg % P;
    int oh = p / OHW, ow = p % OHW;

    const uint4* xb = g_xb + n * HW;
    uint4 xt[9]; unsigned msk[9]; int nv = 0;
#pragma unroll
    for (int t = 0; t < 9; t++) {
        int ih = 2 * oh - 1 + t / 3, iw = 2 * ow - 1 + t % 3;   // <= 55 always
        bool v = (ih >= 0) && (iw >= 0);
        if (v) { xt[t] = ldg4(&xb[ih * WIN + iw]); msk[t] = 0xFFFFFFFFu; nv++; }
        else   { xt[t] = make_uint4(0u,0u,0u,0u); msk[t] = 0u; }
    }
    uint4 xc = ldg4(&xb[(2 * oh) * WIN + (2 * ow)]);  // shortcut tap
    int base = CIN * nv;
    size_t outOff = ((size_t)n * CO + cb) * P + p;

    for (int c = 0; c < 64; c++) {
        int d = 0;
#pragma unroll
        for (int t = 0; t < 9; t++) {
            uint4 w = sw[c * 9 + t];
            unsigned m = msk[t];
            d += __popc((xt[t].x ^ w.x) & m);
            d += __popc((xt[t].y ^ w.y) & m);
            d += __popc((xt[t].z ^ w.z) & m);
            d += __popc((xt[t].w ^ w.w) & m);
        }
        g_c1[outOff + (size_t)c * P] = (short)(base - 2 * d);
        uint4 wb = sws[c];
        int ds = __popc(xc.x ^ wb.x) + __popc(xc.y ^ wb.y)
               + __popc(xc.z ^ wb.z) + __popc(xc.w ^ wb.w);
        g_sc[outOff + (size_t)c * P] = (short)(CIN - 2 * ds);
    }
}

// BN1 stats partials: block = (channel, quarter), exact integer sums
__global__ void stats1_kernel() {
    int co = blockIdx.x, q = blockIdx.y;
    int base = q * (NTOT / 4);                      // 12544 pixels per quarter
    int s = 0, sq = 0;                              // per-thread sq <= 6.5e7, fits
    for (int j = threadIdx.x; j < NTOT / 4; j += 256) {
        int jj = base + j;
        int n = jj / P, pp = jj % P;
        int v = __ldg(&g_c1[((size_t)n * CO + co) * P + pp]);
        s += v; sq += v * v;
    }
    __shared__ int rs[256];
    __shared__ long long rq[256];
    rs[threadIdx.x] = s; rq[threadIdx.x] = (long long)sq; __syncthreads();
    for (int st = 128; st > 0; st >>= 1) {
        if (threadIdx.x < st) { rs[threadIdx.x] += rs[threadIdx.x + st];
                                rq[threadIdx.x] += rq[threadIdx.x + st]; }
        __syncthreads();
    }
    if (threadIdx.x == 0) { g_p1s[q * CO + co] = rs[0]; g_p1q[q * CO + co] = rq[0]; }
}

// finalize alphas + BN1 fold (deterministic fixed-order sums)
__global__ void finalize1_kernel(const float* __restrict__ g1,
                                 const float* __restrict__ b1) {
    __shared__ float al[3];
    int tid = threadIdx.x;
    if (tid < 3) {
        int s0 = (tid == 0) ? 0 : (tid == 1) ? 36 : 108;
        int e0 = (tid == 0) ? 36 : (tid == 1) ? 108 : 112;
        float a = 0.0f;
        for (int i = s0; i < e0; i++) a += g_apart[i];
        float cnt = (tid == 0) ? CNT_W1 : (tid == 1) ? CNT_W2 : CNT_WS;
        al[tid] = a / cnt;
        g_alpha[tid] = al[tid];
    }
    __syncthreads();
    int co = tid;                                   // exactly 256 threads
    long long S = 0, Q = 0;
    for (int q = 0; q < 4; q++) { S += g_p1s[q * CO + co]; Q += g_p1q[q * CO + co]; }
    float a1 = al[0];
    double cnt = (double)NTOT;
    double m  = (double)S / cnt;
    double e2 = (double)Q / cnt;
    double var = (double)a1 * (double)a1 * (e2 - m * m);
    float inv = (float)(1.0 / sqrt(var + 1e-5));
    float mu  = (float)((double)a1 * m);
    g_A1[co] = g1[co] * inv * a1;
    g_B1[co] = b1[co] - g1[co] * inv * mu;
}

// binarize BN1 output + pack 256 channel bits per pixel
__global__ void bin2_kernel() {
    __shared__ float sA[CO], sB[CO];
    int tid = threadIdx.x;
    sA[tid] = g_A1[tid]; sB[tid] = g_B1[tid];
    __syncthreads();
    int pg = blockIdx.x * 256 + tid;
    if (pg >= NTOT) return;
    int n = pg / P, pp = pg % P;
    const short* c1 = g_c1 + (size_t)n * CO * P + pp;
    unsigned wd[8] = {0u,0u,0u,0u,0u,0u,0u,0u};
#pragma unroll 8
    for (int c = 0; c < CO; c++) {
        float v = fmaf(sA[c], (float)__ldg(&c1[(size_t)c * P]), sB[c]);
        wd[c >> 5] |= (v < 0.0f ? 1u : 0u) << (c & 31);
    }
    g_xb2[(size_t)pg * 2]     = make_uint4(wd[0], wd[1], wd[2], wd[3]);
    g_xb2[(size_t)pg * 2 + 1] = make_uint4(wd[4], wd[5], wd[6], wd[7]);
}

// conv2 (3x3 s1 p1, 256->256): integer result only; 64 channels per block
__global__ void __launch_bounds__(128) conv2_kernel() {
    __shared__ uint4 sw[64 * 18];                   // 18.4KB
    int cb = blockIdx.y * 64;
    for (int i = threadIdx.x; i < 64 * 18; i += 128)
        sw[i] = ldg4(&g_wb2[(size_t)cb * 18 + i]);
    __syncthreads();
    int pg = blockIdx.x * 128 + threadIdx.x;
    if (pg >= NTOT) return;
    int n = pg / P, p = pg % P;
    int oh = p / OHW, ow = p % OHW;

    uint4 xt[9][2]; unsigned msk[9]; int nv = 0;
#pragma unroll
    for (int t = 0; t < 9; t++) {
        int ih = oh - 1 + t / 3, iw = ow - 1 + t % 3;
        bool v = (ih >= 0) && (ih < OHW) && (iw >= 0) && (iw < OHW);
        if (v) {
            size_t qx = ((size_t)n * P + ih * OHW + iw) * 2;
            xt[t][0] = ldg4(&g_xb2[qx]); xt[t][1] = ldg4(&g_xb2[qx + 1]);
            msk[t] = 0xFFFFFFFFu; nv++;
        } else {
            xt[t][0] = make_uint4(0u,0u,0u,0u);
            xt[t][1] = make_uint4(0u,0u,0u,0u);
            msk[t] = 0u;
        }
    }
    int base = CO * nv;
    size_t outOff = ((size_t)n * CO + cb) * P + p;

    for (int c = 0; c < 64; c++) {
        int d = 0;
#pragma unroll
        for (int t = 0; t < 9; t++) {
            uint4 w0 = sw[(c * 9 + t) * 2];
            uint4 w1b = sw[(c * 9 + t) * 2 + 1];
            unsigned m = msk[t];
            d += __popc((xt[t][0].x ^ w0.x) & m) + __popc((xt[t][0].y ^ w0.y) & m)
               + __popc((xt[t][0].z ^ w0.z) & m) + __popc((xt[t][0].w ^ w0.w) & m);
            d += __popc((xt[t][1].x ^ w1b.x) & m) + __popc((xt[t][1].y ^ w1b.y) & m)
               + __popc((xt[t][1].z ^ w1b.z) & m) + __popc((xt[t][1].w ^ w1b.w) & m);
        }
        g_c2[outOff + (size_t)c * P] = (short)(base - 2 * d);
    }
}

// BN2 stats partials: 5 exact integer sums of (s2, sc) per channel
__global__ void stats2_kernel() {
    int co = blockIdx.x, q = blockIdx.y;
    const int GRP = NTOT / 4 / 8;                   // 1568 uint4-groups per quarter
    int s2 = 0, sc = 0, scc = 0, s22 = 0, s2c = 0;  // all fit int per-thread
    for (int j = threadIdx.x; j < GRP; j += 256) {
        int g = q * GRP + j;                        // global 8-elem group
        int n = g / (P / 8);
        int pp = (g % (P / 8)) * 8;
        size_t off = ((size_t)n * CO + co) * P + pp;
        uint4 u2 = ldg4((const uint4*)(g_c2 + off));
        uint4 us = ldg4((const uint4*)(g_sc + off));
        const unsigned* a2w = &u2.x;
        const unsigned* asw = &us.x;
#pragma unroll
        for (int k = 0; k < 4; k++) {
            int v2l = (int)(short)(a2w[k] & 0xFFFFu);
            int v2h = ((int)a2w[k]) >> 16;
            int vsl = (int)(short)(asw[k] & 0xFFFFu);
            int vsh = ((int)asw[k]) >> 16;
            s2 += v2l + v2h; sc += vsl + vsh;
            s22 += v2l * v2l + v2h * v2h;
            scc += vsl * vsl + vsh * vsh;
            s2c += v2l * vsl + v2h * vsh;
        }
    }
    __shared__ long long r22[256], r2c[256];
    __shared__ int r2[256], rc[256], rcc[256];
    r22[threadIdx.x] = s22; r2c[threadIdx.x] = s2c;
    r2[threadIdx.x] = s2; rc[threadIdx.x] = sc; rcc[threadIdx.x] = scc;
    __syncthreads();
    for (int st = 128; st > 0; st >>= 1) {
        if (threadIdx.x < st) {
            r22[threadIdx.x] += r22[threadIdx.x + st];
            r2c[threadIdx.x] += r2c[threadIdx.x + st];
            r2[threadIdx.x]  += r2[threadIdx.x + st];
            rc[threadIdx.x]  += rc[threadIdx.x + st];
            rcc[threadIdx.x] += rcc[threadIdx.x + st];
        }
        __syncthreads();
    }
    if (threadIdx.x == 0) {
        long long* dst = g_p2 + (size_t)(q * CO + co) * 5;
        dst[0] = r2[0]; dst[1] = r22[0]; dst[2] = rc[0]; dst[3] = rcc[0]; dst[4] = r2c[0];
    }
}

__global__ void finalize2_kernel(const float* __restrict__ g2,
                                 const float* __restrict__ b2) {
    int co = threadIdx.x;                           // 256 threads
    long long S2 = 0, S22 = 0, Sc = 0, Scc = 0, S2c = 0;
    for (int q = 0; q < 4; q++) {
        const long long* src = g_p2 + (size_t)(q * CO + co) * 5;
        S2 += src[0]; S22 += src[1]; Sc += src[2]; Scc += src[3]; S2c += src[4];
    }
    double a2 = (double)g_alpha[1], as = (double)g_alpha[2];
    double cnt = (double)NTOT;
    double Sv  = a2 * (double)S2 + as * (double)Sc;
    double Svv = a2 * a2 * (double)S22 + 2.0 * a2 * as * (double)S2c + as * as * (double)Scc;
    double m   = Sv / cnt;
    double var = Svv / cnt - m * m;
    float inv  = (float)(1.0 / sqrt(var + 1e-5));
    float gi   = g2[co] * inv;
    g_cA[co] = gi * (float)a2;
    g_cS[co] = gi * (float)as;
    g_cB[co] = b2[co] - gi * (float)m;
}

// final epilogue: out = cA*s2 + cS*sc + cB, 8 elems/thread
__global__ void bnout_kernel(float* __restrict__ out) {
    int grp = blockIdx.x * 256 + threadIdx.x;
    if (grp >= NOUT / 8) return;
    int chan = (grp / (P / 8)) % CO;
    float a = g_cA[chan], s = g_cS[chan], b = g_cB[chan];
    uint4 u2 = ldg4(&((const uint4*)g_c2)[grp]);
    uint4 us = ldg4(&((const uint4*)g_sc)[grp]);
    const unsigned* a2w = &u2.x;
    const unsigned* asw = &us.x;
    float r[8];
#pragma unroll
    for (int k = 0; k < 4; k++) {
        int v2l = (int)(short)(a2w[k] & 0xFFFFu);
        int v2h = ((int)a2w[k]) >> 16;
        int vsl = (int)(short)(asw[k] & 0xFFFFu);
        int vsh = ((int)asw[k]) >> 16;
        r[2*k]   = fmaf(a, (float)v2l, fmaf(s, (float)vsl, b));
        r[2*k+1] = fmaf(a, (float)v2h, fmaf(s, (float)vsh, b));
    }
    float4* o = (float4*)(out + (size_t)grp * 8);
    o[0] = make_float4(r[0], r[1], r[2], r[3]);
    o[1] = make_float4(r[4], r[5], r[6], r[7]);
}

// ---------------- launch ----------------
extern "C" void kernel_launch(void* const* d_in, const int* in_sizes, int n_in,
                              void* d_out, int out_size) {
    const float* x  = (const float*)d_in[0];
    const float* w1 = (const float*)d_in[1];
    const float* g1 = (const float*)d_in[2];
    const float* b1 = (const float*)d_in[3];
    const float* w2 = (const float*)d_in[4];
    const float* g2 = (const float*)d_in[5];
    const float* b2 = (const float*)d_in[6];
    const float* ws = (const float*)d_in[7];
    float* out = (float*)d_out;

    alpha_reduce_kernel<<<112, 256>>>(w1, w2, ws);
    pack_x_kernel<<<NPIX / 256, 256>>>(x);
    pack_w_kernel<<<19, 256>>>(w1, w2, ws);
    conv1_kernel<<<dim3(NTOT / 128, 4), 128>>>();
    stats1_kernel<<<dim3(CO, 4), 256>>>();
    finalize1_kernel<<<1, 256>>>(g1, b1);
    bin2_kernel<<<NTOT / 256, 256>>>();
    conv2_kernel<<<dim3(NTOT / 128, 4), 128>>>();
    stats2_kernel<<<dim3(CO, 4), 256>>>();
    finalize2_kernel<<<1, 256>>>(g2, b2);
    bnout_kernel<<<NOUT / 8 / 256, 256>>>(out);
}

// round 13
// speedup vs baseline: 1.2437x; 1.2437x over previous
#include <cuda_runtime.h>
#include <cuda_bf16.h>
#include <stdint.h>

// ---------------- problem constants ----------------
#define NB   64      // batch
#define CIN  128
#define HIN  56
#define WIN  56
#define CO   256
#define OHW  28
#define P    784     // 28*28
#define HW   3136    // 56*56
#define NPIX (NB*HW)         // 200704
#define NTOT (NB*P)          // 50176 output pixels
#define NOUT (NB*CO*P)       // 12845056
#define CNT_W1 294912.0f
#define CNT_W2 589824.0f
#define CNT_WS 32768.0f

// ---------------- scratch (device globals; no allocations allowed) ----------
__device__ uint4  g_xb [NB*HW];                 // packed sign bits of x (3.2MB)
__device__ uint4  g_wb1[CO*9];                  // packed w1 signs
__device__ uint4  g_wb2[CO*9*2];                // packed w2 signs (256b per co,tap)
__device__ uint4  g_wbs[CO];                    // packed ws signs
__device__ __align__(16) short g_c1[NOUT];      // conv1 integer result (25.7MB)
__device__ __align__(16) short g_sc[NOUT];      // shortcut integer result (25.7MB)
__device__ __align__(16) short g_c2p[2*NOUT];   // conv2 half partials (51.4MB)
__device__ uint4  g_xb2[NTOT*2];                // packed BN1-output signs (1.6MB)
__device__ float  g_apart[112];                 // alpha block partials
__device__ float  g_alpha[3];                   // a1, a2, as
__device__ int       g_p1s[4*CO];               // BN1 stats partials
__device__ long long g_p1q[4*CO];
__device__ long long g_p2 [4*CO*5];             // BN2 stats partials (5 sums)
__device__ float  g_A1[CO], g_B1[CO];           // BN1 folded: v = A1*s + B1
__device__ float  g_cA[CO], g_cS[CO], g_cB[CO]; // out = cA*s2 + cS*sc + cB

__device__ __forceinline__ uint4 ldg4(const uint4* p) { return __ldg(p); }
__device__ __forceinline__ unsigned maj3(unsigned a, unsigned b, unsigned c) {
    return (a & b) | (c & (a | b));          // single LOP3
}
__device__ __forceinline__ unsigned xor3(unsigned a, unsigned b, unsigned c) {
    return a ^ b ^ c;                        // single LOP3
}

// CSA-compressed popcount of 36 masked-xor words (9 taps x 4 lanes).
// Exact: sum popc((xw[t][l]^w[t][l])&msk[t]) computed with 16 POPCs.
__device__ __forceinline__ int popc36_csa(const unsigned xw[9][4],
                                          const unsigned msk[9],
                                          const uint4* swc) {
    unsigned M[3][4], E[3][4];
#pragma unroll
    for (int g = 0; g < 3; g++) {
        uint4 W0 = swc[3*g+0], W1 = swc[3*g+1], W2 = swc[3*g+2];
        unsigned w0[4] = {W0.x, W0.y, W0.z, W0.w};
        unsigned w1[4] = {W1.x, W1.y, W1.z, W1.w};
        unsigned w2[4] = {W2.x, W2.y, W2.z, W2.w};
        unsigned m0 = msk[3*g+0], m1 = msk[3*g+1], m2 = msk[3*g+2];
#pragma unroll
        for (int l = 0; l < 4; l++) {
            unsigned a = (xw[3*g+0][l] ^ w0[l]) & m0;   // LOP3
            unsigned b = (xw[3*g+1][l] ^ w1[l]) & m1;   // LOP3
            unsigned c = (xw[3*g+2][l] ^ w2[l]) & m2;   // LOP3
            M[g][l] = maj3(a, b, c);                     // weight 2
            E[g][l] = xor3(a, b, c);                     // weight 1
        }
    }
    int S4 = 0, S2 = 0, S1 = 0;
#pragma unroll
    for (int l = 0; l < 4; l++) {
        S4 += __popc(maj3(M[0][l], M[1][l], M[2][l]));   // weight 4
        S2 += __popc(xor3(M[0][l], M[1][l], M[2][l]));   // weight 2
        S2 += __popc(maj3(E[0][l], E[1][l], E[2][l]));   // weight 2
        S1 += __popc(xor3(E[0][l], E[1][l], E[2][l]));   // weight 1
    }
    return (S4 << 2) + (S2 << 1) + S1;                   // total popcount
}

// ---------------- kernels ----------------

__global__ void alpha_reduce_kernel(const float* __restrict__ w1,
                                    const float* __restrict__ w2,
                                    const float* __restrict__ ws) {
    int b = blockIdx.x;
    const float* src; int off;
    if (b < 36)       { src = w1; off = b * 8192; }
    else if (b < 108) { src = w2; off = (b - 36) * 8192; }
    else              { src = ws; off = (b - 108) * 8192; }
    float s = 0.0f;
    for (int i = threadIdx.x; i < 8192; i += 256) s += fabsf(src[off + i]);
    __shared__ float red[256];
    red[threadIdx.x] = s; __syncthreads();
    for (int st = 128; st > 0; st >>= 1) {
        if (threadIdx.x < st) red[threadIdx.x] += red[threadIdx.x + st];
        __syncthreads();
    }
    if (threadIdx.x == 0) g_apart[b] = red[0];
}

__global__ void pack_x_kernel(const float* __restrict__ x) {
    int idx = blockIdx.x * 256 + threadIdx.x;
    if (idx >= NPIX) return;
    int n = idx / HW, hw = idx % HW;
    unsigned wd[4] = {0u, 0u, 0u, 0u};
    const float* px = x + (size_t)n * CIN * HW + hw;
#pragma unroll 4
    for (int c = 0; c < CIN; c++) {
        unsigned neg = (px[(size_t)c * HW] < 0.0f) ? 1u : 0u;
        wd[c >> 5] |= neg << (c & 31);
    }
    g_xb[idx] = make_uint4(wd[0], wd[1], wd[2], wd[3]);
}

__global__ void pack_w_kernel(const float* __restrict__ w1,
                              const float* __restrict__ w2,
                              const float* __restrict__ ws) {
    int i = blockIdx.x * 256 + threadIdx.x;
    if (i < 2304) {                       // w1: i = co*9 + tap
        int co = i / 9, t = i % 9;
        unsigned wd[4] = {0u, 0u, 0u, 0u};
        for (int c = 0; c < CIN; c++) {
            unsigned neg = (w1[((size_t)co * CIN + c) * 9 + t] < 0.0f) ? 1u : 0u;
            wd[c >> 5] |= neg << (c & 31);
        }
        g_wb1[i] = make_uint4(wd[0], wd[1], wd[2], wd[3]);
    } else if (i < 4608) {                // w2
        int j = i - 2304; int co = j / 9, t = j % 9;
        unsigned wd[8] = {0u,0u,0u,0u,0u,0u,0u,0u};
        for (int c = 0; c < CO; c++) {
            unsigned neg = (w2[((size_t)co * CO + c) * 9 + t] < 0.0f) ? 1u : 0u;
            wd[c >> 5] |= neg << (c & 31);
        }
        g_wb2[(size_t)j * 2]     = make_uint4(wd[0], wd[1], wd[2], wd[3]);
        g_wb2[(size_t)j * 2 + 1] = make_uint4(wd[4], wd[5], wd[6], wd[7]);
    } else if (i < 4864) {                // ws
        int co = i - 4608;
        unsigned wd[4] = {0u, 0u, 0u, 0u};
        for (int c = 0; c < CIN; c++) {
            unsigned neg = (ws[(size_t)co * CIN + c] < 0.0f) ? 1u : 0u;
            wd[c >> 5] |= neg << (c & 31);
        }
        g_wbs[co] = make_uint4(wd[0], wd[1], wd[2], wd[3]);
    }
}

// conv1 (3x3 s2 p1, 128->256) + 1x1 s2 shortcut; CSA-compressed popcounts
__global__ void __launch_bounds__(128) conv1_kernel() {
    __shared__ uint4 sw[64 * 9];
    __shared__ uint4 sws[64];
    int cb = blockIdx.y * 64;
    for (int i = threadIdx.x; i < 64 * 9; i += 128) sw[i] = ldg4(&g_wb1[cb * 9 + i]);
    if (threadIdx.x < 64) sws[threadIdx.x] = ldg4(&g_wbs[cb + threadIdx.x]);
    __syncthreads();
    int pg = blockIdx.x * 128 + threadIdx.x;
    if (pg >= NTOT) return;
    int n = pg / P, p = pg % P;
    int oh = p / OHW, ow = p % OHW;

    const uint4* xb = g_xb + n * HW;
    unsigned xw[9][4]; unsigned msk[9]; int nv = 0;
#pragma unroll
    for (int t = 0; t < 9; t++) {
        int ih = 2 * oh - 1 + t / 3, iw = 2 * ow - 1 + t % 3;   // <= 55 always
        bool v = (ih >= 0) && (iw >= 0);
        uint4 xv = make_uint4(0u,0u,0u,0u);
        if (v) { xv = ldg4(&xb[ih * WIN + iw]); msk[t] = 0xFFFFFFFFu; nv++; }
        else   { msk[t] = 0u; }
        xw[t][0] = xv.x; xw[t][1] = xv.y; xw[t][2] = xv.z; xw[t][3] = xv.w;
    }
    uint4 xc = ldg4(&xb[(2 * oh) * WIN + (2 * ow)]);  // shortcut tap
    int base = CIN * nv;
    size_t outOff = ((size_t)n * CO + cb) * P + p;

    for (int c = 0; c < 64; c++) {
        int d = popc36_csa(xw, msk, &sw[c * 9]);
        g_c1[outOff + (size_t)c * P] = (short)(base - 2 * d);
        uint4 wb = sws[c];
        unsigned s0 = xc.x ^ wb.x, s1 = xc.y ^ wb.y;
        unsigned s2w = xc.z ^ wb.z, s3 = xc.w ^ wb.w;
        int ds = 2 * __popc(maj3(s0, s1, s2w)) + __popc(xor3(s0, s1, s2w))
               + __popc(s3);
        g_sc[outOff + (size_t)c * P] = (short)(CIN - 2 * ds);
    }
}

// BN1 stats partials: block = (channel, quarter), exact integer sums
__global__ void stats1_kernel() {
    int co = blockIdx.x, q = blockIdx.y;
    int base = q * (NTOT / 4);
    int s = 0, sq = 0;
    for (int j = threadIdx.x; j < NTOT / 4; j += 256) {
        int jj = base + j;
        int n = jj / P, pp = jj % P;
        int v = __ldg(&g_c1[((size_t)n * CO + co) * P + pp]);
        s += v; sq += v * v;
    }
    __shared__ int rs[256];
    __shared__ long long rq[256];
    rs[threadIdx.x] = s; rq[threadIdx.x] = (long long)sq; __syncthreads();
    for (int st = 128; st > 0; st >>= 1) {
        if (threadIdx.x < st) { rs[threadIdx.x] += rs[threadIdx.x + st];
                                rq[threadIdx.x] += rq[threadIdx.x + st]; }
        __syncthreads();
    }
    if (threadIdx.x == 0) { g_p1s[q * CO + co] = rs[0]; g_p1q[q * CO + co] = rq[0]; }
}

__global__ void finalize1_kernel(const float* __restrict__ g1,
                                 const float* __restrict__ b1) {
    __shared__ float al[3];
    int tid = threadIdx.x;
    if (tid < 3) {
        int s0 = (tid == 0) ? 0 : (tid == 1) ? 36 : 108;
        int e0 = (tid == 0) ? 36 : (tid == 1) ? 108 : 112;
        float a = 0.0f;
        for (int i = s0; i < e0; i++) a += g_apart[i];
        float cnt = (tid == 0) ? CNT_W1 : (tid == 1) ? CNT_W2 : CNT_WS;
        al[tid] = a / cnt;
        g_alpha[tid] = al[tid];
    }
    __syncthreads();
    int co = tid;
    long long S = 0, Q = 0;
    for (int q = 0; q < 4; q++) { S += g_p1s[q * CO + co]; Q += g_p1q[q * CO + co]; }
    float a1 = al[0];
    double cnt = (double)NTOT;
    double m  = (double)S / cnt;
    double e2 = (double)Q / cnt;
    double var = (double)a1 * (double)a1 * (e2 - m * m);
    float inv = (float)(1.0 / sqrt(var + 1e-5));
    float mu  = (float)((double)a1 * m);
    g_A1[co] = g1[co] * inv * a1;
    g_B1[co] = b1[co] - g1[co] * inv * mu;
}

// binarize BN1 output + pack 256 channel bits per pixel
__global__ void bin2_kernel() {
    __shared__ float sA[CO], sB[CO];
    int tid = threadIdx.x;
    sA[tid] = g_A1[tid]; sB[tid] = g_B1[tid];
    __syncthreads();
    int pg = blockIdx.x * 256 + tid;
    if (pg >= NTOT) return;
    int n = pg / P, pp = pg % P;
    const short* c1 = g_c1 + (size_t)n * CO * P + pp;
    unsigned wd[8] = {0u,0u,0u,0u,0u,0u,0u,0u};
#pragma unroll 8
    for (int c = 0; c < CO; c++) {
        float v = fmaf(sA[c], (float)__ldg(&c1[(size_t)c * P]), sB[c]);
        wd[c >> 5] |= (v < 0.0f ? 1u : 0u) << (c & 31);
    }
    g_xb2[(size_t)pg * 2]     = make_uint4(wd[0], wd[1], wd[2], wd[3]);
    g_xb2[(size_t)pg * 2 + 1] = make_uint4(wd[4], wd[5], wd[6], wd[7]);
}

// conv2 half (3x3 s1 p1, 128 input bits): blockIdx.z = half, CSA popcounts
__global__ void __launch_bounds__(128) conv2_kernel() {
    __shared__ uint4 sw[64 * 9];
    int cb = blockIdx.y * 64;
    int h  = blockIdx.z;
    for (int i = threadIdx.x; i < 64 * 9; i += 128)
        sw[i] = ldg4(&g_wb2[(size_t)(cb * 9 + i) * 2 + h]);
    __syncthreads();
    int pg = blockIdx.x * 128 + threadIdx.x;
    if (pg >= NTOT) return;
    int n = pg / P, p = pg % P;
    int oh = p / OHW, ow = p % OHW;

    unsigned xw[9][4]; unsigned msk[9]; int nv = 0;
#pragma unroll
    for (int t = 0; t < 9; t++) {
        int ih = oh - 1 + t / 3, iw = ow - 1 + t % 3;
        bool v = (ih >= 0) && (ih < OHW) && (iw >= 0) && (iw < OHW);
        uint4 xv = make_uint4(0u,0u,0u,0u);
        if (v) {
            xv = ldg4(&g_xb2[((size_t)n * P + ih * OHW + iw) * 2 + h]);
            msk[t] = 0xFFFFFFFFu; nv++;
        } else msk[t] = 0u;
        xw[t][0] = xv.x; xw[t][1] = xv.y; xw[t][2] = xv.z; xw[t][3] = xv.w;
    }
    int base = 128 * nv;
    size_t outOff = (size_t)h * NOUT + ((size_t)n * CO + cb) * P + p;

    for (int c = 0; c < 64; c++) {
        int d = popc36_csa(xw, msk, &sw[c * 9]);
        g_c2p[outOff + (size_t)c * P] = (short)(base - 2 * d);
    }
}

// BN2 stats partials: 5 exact integer sums of (s2 = a+b, sc) per channel
__global__ void stats2_kernel() {
    int co = blockIdx.x, q = blockIdx.y;
    const int GRP = NTOT / 4 / 8;                   // 1568 uint4-groups per quarter
    int s2 = 0, sc = 0, scc = 0, s22 = 0, s2c = 0;
    for (int j = threadIdx.x; j < GRP; j += 256) {
        int g = q * GRP + j;
        int n = g / (P / 8);
        int pp = (g % (P / 8)) * 8;
        size_t off = ((size_t)n * CO + co) * P + pp;
        uint4 ua = ldg4((const uint4*)(g_c2p + off));
        uint4 ub = ldg4((const uint4*)(g_c2p + (size_t)NOUT + off));
        uint4 us = ldg4((const uint4*)(g_sc + off));
        const unsigned* aw = &ua.x;
        const unsigned* bw = &ub.x;
        const unsigned* cw = &us.x;
#pragma unroll
        for (int k = 0; k < 4; k++) {
            int v2l = (int)(short)(aw[k] & 0xFFFFu) + (int)(short)(bw[k] & 0xFFFFu);
            int v2h = (((int)aw[k]) >> 16) + (((int)bw[k]) >> 16);
            int vsl = (int)(short)(cw[k] & 0xFFFFu);
            int vsh = ((int)cw[k]) >> 16;
            s2 += v2l + v2h; sc += vsl + vsh;
            s22 += v2l * v2l + v2h * v2h;
            scc += vsl * vsl + vsh * vsh;
            s2c += v2l * vsl + v2h * vsh;
        }
    }
    __shared__ long long r22[256], r2c[256];
    __shared__ int r2[256], rc[256], rcc[256];
    r22[threadIdx.x] = s22; r2c[threadIdx.x] = s2c;
    r2[threadIdx.x] = s2; rc[threadIdx.x] = sc; rcc[threadIdx.x] = scc;
    __syncthreads();
    for (int st = 128; st > 0; st >>= 1) {
        if (threadIdx.x < st) {
            r22[threadIdx.x] += r22[threadIdx.x + st];
            r2c[threadIdx.x] += r2c[threadIdx.x + st];
            r2[threadIdx.x]  += r2[threadIdx.x + st];
            rc[threadIdx.x]  += rc[threadIdx.x + st];
            rcc[threadIdx.x] += rcc[threadIdx.x + st];
        }
        __syncthreads();
    }
    if (threadIdx.x == 0) {
        long long* dst = g_p2 + (size_t)(q * CO + co) * 5;
        dst[0] = r2[0]; dst[1] = r22[0]; dst[2] = rc[0]; dst[3] = rcc[0]; dst[4] = r2c[0];
    }
}

__global__ void finalize2_kernel(const float* __restrict__ g2,
                                 const float* __restrict__ b2) {
    int co = threadIdx.x;
    long long S2 = 0, S22 = 0, Sc = 0, Scc = 0, S2c = 0;
    for (int q = 0; q < 4; q++) {
        const long long* src = g_p2 + (size_t)(q * CO + co) * 5;
        S2 += src[0]; S22 += src[1]; Sc += src[2]; Scc += src[3]; S2c += src[4];
    }
    double a2 = (double)g_alpha[1], as = (double)g_alpha[2];
    double cnt = (double)NTOT;
    double Sv  = a2 * (double)S2 + as * (double)Sc;
    double Svv = a2 * a2 * (double)S22 + 2.0 * a2 * as * (double)S2c + as * as * (double)Scc;
    double m   = Sv / cnt;
    double var = Svv / cnt - m * m;
    float inv  = (float)(1.0 / sqrt(var + 1e-5));
    float gi   = g2[co] * inv;
    g_cA[co] = gi * (float)a2;
    g_cS[co] = gi * (float)as;
    g_cB[co] = b2[co] - gi * (float)m;
}

// final epilogue: out = cA*(a+b) + cS*sc + cB, 8 elems/thread
__global__ void bnout_kernel(float* __restrict__ out) {
    int grp = blockIdx.x * 256 + threadIdx.x;
    if (grp >= NOUT / 8) return;
    int chan = (grp / (P / 8)) % CO;
    float a = g_cA[chan], s = g_cS[chan], b = g_cB[chan];
    uint4 ua = ldg4(&((const uint4*)g_c2p)[grp]);
    uint4 ub = ldg4(&((const uint4*)(g_c2p + NOUT))[grp]);
    uint4 us = ldg4(&((const uint4*)g_sc)[grp]);
    const unsigned* aw = &ua.x;
    const unsigned* bw = &ub.x;
    const unsigned* cw = &us.x;
    float r[8];
#pragma unroll
    for (int k = 0; k < 4; k++) {
        int v2l = (int)(short)(aw[k] & 0xFFFFu) + (int)(short)(bw[k] & 0xFFFFu);
        int v2h = (((int)aw[k]) >> 16) + (((int)bw[k]) >> 16);
        int vsl = (int)(short)(cw[k] & 0xFFFFu);
        int vsh = ((int)cw[k]) >> 16;
        r[2*k]   = fmaf(a, (float)v2l, fmaf(s, (float)vsl, b));
        r[2*k+1] = fmaf(a, (float)v2h, fmaf(s, (float)vsh, b));
    }
    float4* o = (float4*)(out + (size_t)grp * 8);
    o[0] = make_float4(r[0], r[1], r[2], r[3]);
    o[1] = make_float4(r[4], r[5], r[6], r[7]);
}

// ---------------- launch ----------------
extern "C" void kernel_launch(void* const* d_in, const int* in_sizes, int n_in,
                              void* d_out, int out_size) {
    const float* x  = (const float*)d_in[0];
    const float* w1 = (const float*)d_in[1];
    const float* g1 = (const float*)d_in[2];
    const float* b1 = (const float*)d_in[3];
    const float* w2 = (const float*)d_in[4];
    const float* g2 = (const float*)d_in[5];
    const float* b2 = (const float*)d_in[6];
    const float* ws = (const float*)d_in[7];
    float* out = (float*)d_out;

    alpha_reduce_kernel<<<112, 256>>>(w1, w2, ws);
    pack_x_kernel<<<NPIX / 256, 256>>>(x);
    pack_w_kernel<<<19, 256>>>(w1, w2, ws);
    conv1_kernel<<<dim3(NTOT / 128, 4), 128>>>();
    stats1_kernel<<<dim3(CO, 4), 256>>>();
    finalize1_kernel<<<1, 256>>>(g1, b1);
    bin2_kernel<<<NTOT / 256, 256>>>();
    conv2_kernel<<<dim3(NTOT / 128, 4, 2), 128>>>();
    stats2_kernel<<<dim3(CO, 4), 256>>>();
    finalize2_kernel<<<1, 256>>>(g2, b2);
    bnout_kernel<<<NOUT / 8 / 256, 256>>>(out);
}